// round 14
// baseline (speedup 1.0000x reference)
#include <cuda_runtime.h>
#include <cuda_bf16.h>

#define WG_EPS 1e-8f
#define BLK 256

// Sequential-stream read: non-coherent path + 256B L2 promotion hint.
__device__ __forceinline__ float ldg256(const float* p) {
    float v;
    asm("ld.global.nc.L2::256B.f32 %0, [%1];" : "=f"(v) : "l"(p));
    return v;
}
// Streaming (evict-first) store: keep the write stream out of L2's way.
__device__ __forceinline__ void stcs(float* p, float v) {
    asm volatile("st.global.cs.f32 [%0], %1;" :: "l"(p), "f"(v));
}

__global__ __launch_bounds__(BLK) void wasserstein_gaussian_kernel(
    const float* __restrict__ loc1,
    const float* __restrict__ scale1,
    const float* __restrict__ rot1,
    const float* __restrict__ loc2,
    const float* __restrict__ scale2,
    const float* __restrict__ rot2,
    float* __restrict__ out,
    int B)
{
    int b = blockIdx.x * blockDim.x + threadIdx.x;
    if (b >= B) return;

    // ---- loads (R2/R13 structure: proven fastest) with 256B L2 promotion ----
    float l1[3], l2[3], s1[3], s2[3], r1[9], r2[9];
#pragma unroll
    for (int i = 0; i < 3; i++) {
        l1[i] = ldg256(loc1 + 3 * b + i);
        l2[i] = ldg256(loc2 + 3 * b + i);
        s1[i] = fmaxf(ldg256(scale1 + 3 * b + i), WG_EPS);
        s2[i] = fmaxf(ldg256(scale2 + 3 * b + i), WG_EPS);
    }
#pragma unroll
    for (int i = 0; i < 9; i++) {
        r1[i] = ldg256(rot1 + 9 * b + i);
        r2[i] = ldg256(rot2 + 9 * b + i);
    }

    // ---- loc term ----
    float d0 = l1[0] - l2[0], d1 = l1[1] - l2[1], d2 = l1[2] - l2[2];
    float loc_diff2 = d0 * d0 + d1 * d1 + d2 * d2;

    // ---- cov2 = R2 diag(s2) R2^T (6 unique entries) ----
    float cov2[3][3];
#pragma unroll
    for (int i = 0; i < 3; i++) {
#pragma unroll
        for (int k = i; k < 3; k++) {
            float v = r2[3 * i + 0] * s2[0] * r2[3 * k + 0]
                    + r2[3 * i + 1] * s2[1] * r2[3 * k + 1]
                    + r2[3 * i + 2] * s2[2] * r2[3 * k + 2];
            cov2[i][k] = v;
            cov2[k][i] = v;
        }
    }
    float tr_cov2 = cov2[0][0] + cov2[1][1] + cov2[2][2];

    // ---- M = R1^T cov2 R1 ----
    float T[3][3];
#pragma unroll
    for (int j = 0; j < 3; j++)
#pragma unroll
        for (int l = 0; l < 3; l++)
            T[j][l] = cov2[j][0] * r1[0 * 3 + l]
                    + cov2[j][1] * r1[1 * 3 + l]
                    + cov2[j][2] * r1[2 * 3 + l];

    float M[3][3];
#pragma unroll
    for (int i = 0; i < 3; i++)
#pragma unroll
        for (int l = 0; l < 3; l++)
            M[i][l] = r1[0 * 3 + i] * T[0][l]
                    + r1[1 * 3 + i] * T[1][l]
                    + r1[2 * 3 + i] * T[2][l];

    // ---- E = diag(sqrt(s1)) M diag(sqrt(s1)), symmetrized + EPS*I ----
    float q0 = sqrtf(s1[0]), q1 = sqrtf(s1[1]), q2 = sqrtf(s1[2]);
    float a00 = s1[0] * M[0][0] + WG_EPS;
    float a11 = s1[1] * M[1][1] + WG_EPS;
    float a22 = s1[2] * M[2][2] + WG_EPS;
    float a01 = q0 * q1 * 0.5f * (M[0][1] + M[1][0]);
    float a02 = q0 * q2 * 0.5f * (M[0][2] + M[2][0]);
    float a12 = q1 * q2 * 0.5f * (M[1][2] + M[2][1]);

    // ---- s = tr(E^{1/2}) via invariants + Newton (no eigenvalues, no trig) ----
    // s = sum sqrt(lambda_i) is the largest root of
    //   f(s) = s^4 - 2*I1*s^2 - 8*sqrt(I3)*s + (I1^2 - 4*I2) = 0
    // Start from the upper bound s0 = sqrt(I1 + 2*sqrt(3*I2)) >= s*;
    // f is increasing & convex on [s*, inf) -> monotone Newton descent.
    float I1 = a00 + a11 + a22;
    float I2 = (a00 * a11 - a01 * a01)
             + (a00 * a22 - a02 * a02)
             + (a11 * a22 - a12 * a12);
    float I3 = a00 * (a11 * a22 - a12 * a12)
             - a01 * (a01 * a22 - a12 * a02)
             + a02 * (a01 * a12 - a11 * a02);
    I1 = fmaxf(I1, 3.0f * WG_EPS);
    I2 = fmaxf(I2, 0.0f);
    I3 = fmaxf(I3, 0.0f);

    float c8 = 8.0f * sqrtf(I3);
    float K  = I1 * I1 - 4.0f * I2;
    float s  = sqrtf(I1 + 2.0f * sqrtf(3.0f * I2));   // >= s*

#pragma unroll
    for (int it = 0; it < 5; it++) {
        float s2v = s * s;
        float f   = (s2v - 2.0f * I1) * s2v - c8 * s + K;
        float fp  = s * (4.0f * s2v - 4.0f * I1) - c8;
        s -= f / fmaxf(fp, 1e-20f);
    }
    float sum_sqrt = fmaxf(s, 0.0f);

    // ---- assemble W2 ----
    float cov_w = (s1[0] + s1[1] + s1[2]) + tr_cov2 - 2.0f * sum_sqrt;
    cov_w = fmaxf(cov_w, 0.0f);
    stcs(out + b, sqrtf(fmaxf(loc_diff2 + cov_w, WG_EPS)));
}

extern "C" void kernel_launch(void* const* d_in, const int* in_sizes, int n_in,
                              void* d_out, int out_size)
{
    const float* loc1   = (const float*)d_in[0];
    const float* scale1 = (const float*)d_in[1];
    const float* rot1   = (const float*)d_in[2];
    const float* loc2   = (const float*)d_in[3];
    const float* scale2 = (const float*)d_in[4];
    const float* rot2   = (const float*)d_in[5];
    float* out = (float*)d_out;

    int B = in_sizes[0] / 3;
    int blocks = (B + BLK - 1) / BLK;
    wasserstein_gaussian_kernel<<<blocks, BLK>>>(
        loc1, scale1, rot1, loc2, scale2, rot2, out, B);
}